// round 6
// baseline (speedup 1.0000x reference)
#include <cuda_runtime.h>
#include <cuda_bf16.h>
#include <math.h>
#include <stdint.h>

// Problem constants
#define B_    2
#define S_    2048
#define H_    2048
#define NH    32
#define NKV   8
#define HD    64
#define KVD   512           // NKV * HD
#define MROWS 4096          // B_ * S_

// fp32 scratch
__device__ float g_q [MROWS * H_];
__device__ float g_k [MROWS * KVD];
__device__ float g_v [MROWS * KVD];
__device__ float2 g_cs[S_ * 32];

// bf16 hi/lo splits
__device__ __nv_bfloat16 g_xh [MROWS * H_],  g_xl [MROWS * H_];
__device__ __nv_bfloat16 g_wqh[H_ * H_],     g_wql[H_ * H_];
__device__ __nv_bfloat16 g_wkh[KVD * H_],    g_wkl[KVD * H_];
__device__ __nv_bfloat16 g_wvh[KVD * H_],    g_wvl[KVD * H_];
__device__ __nv_bfloat16 g_woh[H_ * H_],     g_wol[H_ * H_];
__device__ __nv_bfloat16 g_aoh[MROWS * H_],  g_aol[MROWS * H_];
__device__ __nv_bfloat16 g_qh[MROWS * H_],   g_ql[MROWS * H_];
__device__ __nv_bfloat16 g_kh[MROWS * KVD],  g_kl[MROWS * KVD];
__device__ __nv_bfloat16 g_vh[MROWS * KVD],  g_vl[MROWS * KVD];

// ---------------------------------------------------------------------------
// helpers
// ---------------------------------------------------------------------------
__device__ __forceinline__ void mma16816(float* c, const uint32_t* a, const uint32_t* b) {
    asm volatile(
        "mma.sync.aligned.m16n8k16.row.col.f32.bf16.bf16.f32 "
        "{%0,%1,%2,%3}, {%4,%5,%6,%7}, {%8,%9}, {%0,%1,%2,%3};\n"
        : "+f"(c[0]), "+f"(c[1]), "+f"(c[2]), "+f"(c[3])
        : "r"(a[0]), "r"(a[1]), "r"(a[2]), "r"(a[3]), "r"(b[0]), "r"(b[1]));
}
__device__ __forceinline__ void ldsm4(uint32_t* r, uint32_t addr) {
    asm volatile("ldmatrix.sync.aligned.m8n8.x4.shared.b16 {%0,%1,%2,%3}, [%4];\n"
                 : "=r"(r[0]), "=r"(r[1]), "=r"(r[2]), "=r"(r[3]) : "r"(addr));
}
__device__ __forceinline__ void ldsm4t(uint32_t* r, uint32_t addr) {
    asm volatile("ldmatrix.sync.aligned.m8n8.x4.trans.shared.b16 {%0,%1,%2,%3}, [%4];\n"
                 : "=r"(r[0]), "=r"(r[1]), "=r"(r[2]), "=r"(r[3]) : "r"(addr));
}
__device__ __forceinline__ uint32_t pack_bf16(float a, float b) {
    __nv_bfloat162 t = __floats2bfloat162_rn(a, b);
    return *(uint32_t*)&t;
}
__device__ __forceinline__ void cp16(uint32_t dst, const void* src) {
    asm volatile("cp.async.cg.shared.global [%0], [%1], 16;\n" :: "r"(dst), "l"(src));
}

// ---------------------------------------------------------------------------
// hi/lo split: src fp32 -> h,l bf16
// ---------------------------------------------------------------------------
__global__ void split_kernel(const float* __restrict__ src,
                             __nv_bfloat16* __restrict__ h,
                             __nv_bfloat16* __restrict__ l, int n) {
    int i = (blockIdx.x * blockDim.x + threadIdx.x) * 4;
    if (i >= n) return;
    float4 v = *(const float4*)(src + i);
    __nv_bfloat16 h0 = __float2bfloat16(v.x), h1 = __float2bfloat16(v.y);
    __nv_bfloat16 h2 = __float2bfloat16(v.z), h3 = __float2bfloat16(v.w);
    *(__nv_bfloat162*)&h[i]     = __nv_bfloat162(h0, h1);
    *(__nv_bfloat162*)&h[i + 2] = __nv_bfloat162(h2, h3);
    *(__nv_bfloat162*)&l[i] = __nv_bfloat162(
        __float2bfloat16(v.x - __bfloat162float(h0)),
        __float2bfloat16(v.y - __bfloat162float(h1)));
    *(__nv_bfloat162*)&l[i + 2] = __nv_bfloat162(
        __float2bfloat16(v.z - __bfloat162float(h2)),
        __float2bfloat16(v.w - __bfloat162float(h3)));
}

// ---------------------------------------------------------------------------
// Pipelined bf16x3 GEMM: C[M,N] = (Ah+Al)[M,K] @ (Bh+Bl)[N,K]^T
// 128x128 tile, BK=32, 4-stage cp.async pipeline, 256 threads, warp tile 64x32
// ---------------------------------------------------------------------------
#define ST 40                      // smem row stride (bf16 elems)
#define ABYTES (128 * ST * 2)      // 10240 per array
#define STAGEB (4 * ABYTES)        // 40960 per stage
#define SMEMSZ (4 * STAGEB)        // 163840

__global__ void __launch_bounds__(256)
gemm_pre(const __nv_bfloat16* __restrict__ Ah, const __nv_bfloat16* __restrict__ Al,
         const __nv_bfloat16* __restrict__ Bh, const __nv_bfloat16* __restrict__ Bl,
         float* __restrict__ C, int M, int N, int K) {
    extern __shared__ char dsm[];
    const uint32_t smem0 = (uint32_t)__cvta_generic_to_shared(dsm);

    const int t    = threadIdx.x;
    const int lane = t & 31;
    const int w    = t >> 5;
    const int wm   = (w & 1) * 64;
    const int wn   = (w >> 1) * 32;
    const int m0   = blockIdx.y * 128;
    const int n0   = blockIdx.x * 128;

    const int g = lane >> 3, r = lane & 7;
    const int a_moff = (g & 1) * 8 + r;
    const int a_koff = (g >> 1) * 8;
    const int b_noff = (g >> 1) * 8 + r;
    const int b_koff = (g & 1) * 8;

    const int id0 = t, id1 = t + 256;
    const int r0 = id0 >> 2, c0 = (id0 & 3) * 8;
    const int r1 = id1 >> 2, c1 = (id1 & 3) * 8;

    const int nkt = K >> 5;

    auto issue = [&](int kt) {
        int s = kt & 3;
        int k0 = kt << 5;
        uint32_t base = smem0 + s * STAGEB;
        uint32_t d0 = base + (r0 * ST + c0) * 2;
        uint32_t d1 = base + (r1 * ST + c1) * 2;
        size_t ao0 = (size_t)(m0 + r0) * K + k0 + c0;
        size_t ao1 = (size_t)(m0 + r1) * K + k0 + c1;
        size_t bo0 = (size_t)(n0 + r0) * K + k0 + c0;
        size_t bo1 = (size_t)(n0 + r1) * K + k0 + c1;
        cp16(d0,              Ah + ao0); cp16(d1,              Ah + ao1);
        cp16(d0 + ABYTES,     Al + ao0); cp16(d1 + ABYTES,     Al + ao1);
        cp16(d0 + 2 * ABYTES, Bh + bo0); cp16(d1 + 2 * ABYTES, Bh + bo1);
        cp16(d0 + 3 * ABYTES, Bl + bo0); cp16(d1 + 3 * ABYTES, Bl + bo1);
    };

    float acc[4][4][4];
#pragma unroll
    for (int i = 0; i < 4; i++)
#pragma unroll
        for (int j = 0; j < 4; j++)
#pragma unroll
            for (int e = 0; e < 4; e++) acc[i][j][e] = 0.f;

    issue(0); asm volatile("cp.async.commit_group;\n");
    issue(1); asm volatile("cp.async.commit_group;\n");
    issue(2); asm volatile("cp.async.commit_group;\n");

    for (int kt = 0; kt < nkt; kt++) {
        asm volatile("cp.async.wait_group 2;\n");
        __syncthreads();
        if (kt + 3 < nkt) issue(kt + 3);
        asm volatile("cp.async.commit_group;\n");

        const uint32_t base = smem0 + (kt & 3) * STAGEB;
        const uint32_t sAh = base, sAl = base + ABYTES;
        const uint32_t sBh = base + 2 * ABYTES, sBl = base + 3 * ABYTES;

#pragma unroll
        for (int ks = 0; ks < 2; ks++) {
            const int kk = ks * 16;
            uint32_t af[4][4], b1[2][4], b2[2][4];
#pragma unroll
            for (int mi = 0; mi < 4; mi++)
                ldsm4(af[mi], sAh + 2u * ((wm + mi * 16 + a_moff) * ST + kk + a_koff));
#pragma unroll
            for (int nb = 0; nb < 2; nb++) {
                ldsm4(b1[nb], sBh + 2u * ((wn + nb * 16 + b_noff) * ST + kk + b_koff));
                ldsm4(b2[nb], sBl + 2u * ((wn + nb * 16 + b_noff) * ST + kk + b_koff));
            }
#pragma unroll
            for (int mi = 0; mi < 4; mi++)
#pragma unroll
                for (int ni = 0; ni < 4; ni++) {
                    mma16816(acc[mi][ni], af[mi], &b1[ni >> 1][(ni & 1) * 2]);
                    mma16816(acc[mi][ni], af[mi], &b2[ni >> 1][(ni & 1) * 2]);
                }
#pragma unroll
            for (int mi = 0; mi < 4; mi++)
                ldsm4(af[mi], sAl + 2u * ((wm + mi * 16 + a_moff) * ST + kk + a_koff));
#pragma unroll
            for (int mi = 0; mi < 4; mi++)
#pragma unroll
                for (int ni = 0; ni < 4; ni++)
                    mma16816(acc[mi][ni], af[mi], &b1[ni >> 1][(ni & 1) * 2]);
        }
        __syncthreads();
    }

#pragma unroll
    for (int mi = 0; mi < 4; mi++) {
        int row = m0 + wm + mi * 16 + (lane >> 2);
#pragma unroll
        for (int ni = 0; ni < 4; ni++) {
            int col = n0 + wn + ni * 8 + (lane & 3) * 2;
            *(float2*)&C[(size_t)row * N + col]       = make_float2(acc[mi][ni][0], acc[mi][ni][1]);
            *(float2*)&C[(size_t)(row + 8) * N + col] = make_float2(acc[mi][ni][2], acc[mi][ni][3]);
        }
    }
}

// ---------------------------------------------------------------------------
// cos/sin table
// ---------------------------------------------------------------------------
__global__ void cs_table_kernel() {
    int i = blockIdx.x * blockDim.x + threadIdx.x;
    if (i >= S_ * 32) return;
    int pos = i >> 5, p = i & 31;
    double inv = exp(-((double)(2 * p) / 64.0) * log(10000.0));
    double ang = (double)pos * inv;
    g_cs[i] = make_float2((float)cos(ang), (float)sin(ang));
}

// ---------------------------------------------------------------------------
// Fused RoPE (Q,K) + hi/lo split of Q, K, V
// ---------------------------------------------------------------------------
__global__ void rope_split_kernel(const float* __restrict__ q,
                                  const float* __restrict__ k,
                                  const float* __restrict__ v) {
    const int NQ = MROWS * 1024;
    const int NK = MROWS * 256;
    const int NV = MROWS * 256;
    int idx = blockIdx.x * blockDim.x + threadIdx.x;
    if (idx >= NQ + NK + NV) return;

    if (idx < NQ + NK) {
        const float* src; __nv_bfloat16 *dh, *dl;
        int row, p, head, rowstride;
        if (idx < NQ) {
            row = idx >> 10; int rem = idx & 1023;
            head = rem >> 5; p = rem & 31; rowstride = H_;
            src = q; dh = g_qh; dl = g_ql;
        } else {
            int i2 = idx - NQ;
            row = i2 >> 8; int rem = i2 & 255;
            head = rem >> 5; p = rem & 31; rowstride = KVD;
            src = k; dh = g_kh; dl = g_kl;
        }
        size_t base = (size_t)row * rowstride + head * HD;
        int pos = row & (S_ - 1);
        float2 cs = g_cs[pos * 32 + p];
        float x0 = src[base + p], x1 = src[base + p + 32];
        float y0 = x0 * cs.x - x1 * cs.y;
        float y1 = x1 * cs.x + x0 * cs.y;
        __nv_bfloat16 h0 = __float2bfloat16(y0);
        __nv_bfloat16 h1 = __float2bfloat16(y1);
        dh[base + p]      = h0;
        dh[base + p + 32] = h1;
        dl[base + p]      = __float2bfloat16(y0 - __bfloat162float(h0));
        dl[base + p + 32] = __float2bfloat16(y1 - __bfloat162float(h1));
    } else {
        int i2 = idx - NQ - NK;
        size_t base = (size_t)(i2 >> 8) * KVD + (i2 & 255) * 2;
        float x0 = v[base], x1 = v[base + 1];
        __nv_bfloat16 h0 = __float2bfloat16(x0);
        __nv_bfloat16 h1 = __float2bfloat16(x1);
        g_vh[base]     = h0;
        g_vh[base + 1] = h1;
        g_vl[base]     = __float2bfloat16(x0 - __bfloat162float(h0));
        g_vl[base + 1] = __float2bfloat16(x1 - __bfloat162float(h1));
    }
}

// ---------------------------------------------------------------------------
// Tensor-core causal flash attention, 2-stage cp.async pipelined K/V tiles.
// Block = 64 q rows, 4 warps. Stage: Kh,Kl,Vh,Vl each 64xST2 bf16.
// ---------------------------------------------------------------------------
#define ST2 72
#define FA  (64 * ST2 * 2)          // 9216 bytes per array
#define FSTAGE (4 * FA)             // 36864 per stage
#define FSMEM  (2 * FSTAGE)         // 73728

__global__ void __launch_bounds__(128)
flash2(const __nv_bfloat16* __restrict__ Qh, const __nv_bfloat16* __restrict__ Ql,
       const __nv_bfloat16* __restrict__ Kh, const __nv_bfloat16* __restrict__ Kl,
       const __nv_bfloat16* __restrict__ Vh, const __nv_bfloat16* __restrict__ Vl,
       __nv_bfloat16* __restrict__ AOh, __nv_bfloat16* __restrict__ AOl) {
    extern __shared__ char fsm[];
    const uint32_t smem0 = (uint32_t)__cvta_generic_to_shared(fsm);

    const int t = threadIdx.x, lane = t & 31, w = t >> 5;
    const int qb = blockIdx.x, h = blockIdx.y, b = blockIdx.z, kvh = h >> 2;
    const int g = lane >> 3, r = lane & 7;
    const int a_row = (g & 1) * 8 + r, a_k = (g >> 1) * 8;
    const int b_row = (g >> 1) * 8 + r, b_k = (g & 1) * 8;

    const int ntiles = qb + 1;
    const size_t bS = (size_t)(b * S_);

    // ---- stage Q tile through stage-0 Kh/Kl, pull fragments to registers ----
    {
        __nv_bfloat16* s0h = (__nv_bfloat16*)(fsm);
        __nv_bfloat16* s0l = (__nv_bfloat16*)(fsm + FA);
        const size_t qbase = (bS + qb * 64) * H_ + h * HD;
#pragma unroll
        for (int i = 0; i < 4; i++) {
            int idx = t + i * 128;
            int row = idx >> 3, c = (idx & 7) * 8;
            *(uint4*)&s0h[row * ST2 + c] = *(const uint4*)(Qh + qbase + (size_t)row * H_ + c);
            *(uint4*)&s0l[row * ST2 + c] = *(const uint4*)(Ql + qbase + (size_t)row * H_ + c);
        }
    }
    __syncthreads();
    uint32_t qh[4][4], ql[4][4];
#pragma unroll
    for (int ks = 0; ks < 4; ks++) {
        ldsm4(qh[ks], smem0 + 2u * ((w * 16 + a_row) * ST2 + ks * 16 + a_k));
        ldsm4(ql[ks], smem0 + FA + 2u * ((w * 16 + a_row) * ST2 + ks * 16 + a_k));
    }
    __syncthreads();

    // ---- cp.async issue of K/V tile kt into stage kt&1 ----
    auto issue = [&](int kt) {
        if (kt >= ntiles) return;
        uint32_t base = smem0 + (kt & 1) * FSTAGE;
        const size_t kb = (bS + kt * 64) * KVD + kvh * HD;
#pragma unroll
        for (int i = 0; i < 4; i++) {
            int chunk = t + i * 128;           // 0..511
            int row = chunk >> 3, col = (chunk & 7) * 8;
            size_t go = kb + (size_t)row * KVD + col;
            uint32_t so = base + (row * ST2 + col) * 2;
            cp16(so,          Kh + go);
            cp16(so + FA,     Kl + go);
            cp16(so + 2 * FA, Vh + go);
            cp16(so + 3 * FA, Vl + go);
        }
    };

    issue(0); asm volatile("cp.async.commit_group;\n");
    issue(1); asm volatile("cp.async.commit_group;\n");

    float o[8][4];
#pragma unroll
    for (int j = 0; j < 8; j++)
#pragma unroll
        for (int e = 0; e < 4; e++) o[j][e] = 0.f;
    float m0 = -3.0e38f, m1 = -3.0e38f, l0 = 0.f, l1 = 0.f;
    const int qr0 = qb * 64 + w * 16 + (lane >> 2);
    const int qr1 = qr0 + 8;

    for (int kt = 0; kt < ntiles; kt++) {
        asm volatile("cp.async.wait_group 1;\n");
        __syncthreads();

        const uint32_t base = smem0 + (kt & 1) * FSTAGE;
        const uint32_t pKh = base, pKl = base + FA;
        const uint32_t pVh = base + 2 * FA, pVl = base + 3 * FA;
        const int k0 = kt * 64;

        // ---- S = Q K^T (bf16x3) ----
        float s[8][4];
#pragma unroll
        for (int j = 0; j < 8; j++)
#pragma unroll
            for (int e = 0; e < 4; e++) s[j][e] = 0.f;
#pragma unroll
        for (int ks = 0; ks < 4; ks++) {
#pragma unroll
            for (int nb = 0; nb < 4; nb++) {
                uint32_t bh[4], bl[4];
                ldsm4(bh, pKh + 2u * ((nb * 16 + b_row) * ST2 + ks * 16 + b_k));
                ldsm4(bl, pKl + 2u * ((nb * 16 + b_row) * ST2 + ks * 16 + b_k));
#pragma unroll
                for (int hn = 0; hn < 2; hn++) {
                    int j = nb * 2 + hn;
                    mma16816(s[j], qh[ks], bh + hn * 2);
                    mma16816(s[j], qh[ks], bl + hn * 2);
                    mma16816(s[j], ql[ks], bh + hn * 2);
                }
            }
        }

        // ---- scale + causal mask + online softmax ----
        const bool diag = (kt == ntiles - 1);
        float mx0 = -3.0e38f, mx1 = -3.0e38f;
#pragma unroll
        for (int j = 0; j < 8; j++) {
            int colb = k0 + j * 8 + (lane & 3) * 2;
#pragma unroll
            for (int e = 0; e < 4; e++) {
                float val = s[j][e] * 0.125f;
                if (diag) {
                    int col = colb + (e & 1);
                    int qr  = (e < 2) ? qr0 : qr1;
                    if (col > qr) val = -1.0e9f;
                }
                s[j][e] = val;
                if (e < 2) mx0 = fmaxf(mx0, val); else mx1 = fmaxf(mx1, val);
            }
        }
        mx0 = fmaxf(mx0, __shfl_xor_sync(0xffffffffu, mx0, 1));
        mx0 = fmaxf(mx0, __shfl_xor_sync(0xffffffffu, mx0, 2));
        mx1 = fmaxf(mx1, __shfl_xor_sync(0xffffffffu, mx1, 1));
        mx1 = fmaxf(mx1, __shfl_xor_sync(0xffffffffu, mx1, 2));
        float nm0 = fmaxf(m0, mx0), nm1 = fmaxf(m1, mx1);
        float c0 = __expf(m0 - nm0), c1 = __expf(m1 - nm1);
        l0 *= c0; l1 *= c1;
#pragma unroll
        for (int j = 0; j < 8; j++) {
            o[j][0] *= c0; o[j][1] *= c0;
            o[j][2] *= c1; o[j][3] *= c1;
        }
        m0 = nm0; m1 = nm1;
        float rs0 = 0.f, rs1 = 0.f;
#pragma unroll
        for (int j = 0; j < 8; j++) {
#pragma unroll
            for (int e = 0; e < 4; e++) {
                float p = __expf(s[j][e] - ((e < 2) ? m0 : m1));
                s[j][e] = p;
                if (e < 2) rs0 += p; else rs1 += p;
            }
        }
        l0 += rs0; l1 += rs1;

        // ---- P fragments (hi/lo) ----
        uint32_t ph[4][4], pl_[4][4];
#pragma unroll
        for (int kg = 0; kg < 4; kg++) {
#pragma unroll
            for (int q2 = 0; q2 < 2; q2++) {
                int j = 2 * kg + q2;
#pragma unroll
                for (int half = 0; half < 2; half++) {
                    float v0 = s[j][half * 2], v1 = s[j][half * 2 + 1];
                    float h0 = __bfloat162float(__float2bfloat16(v0));
                    float h1 = __bfloat162float(__float2bfloat16(v1));
                    ph[kg][q2 * 2 + half]  = pack_bf16(h0, h1);
                    pl_[kg][q2 * 2 + half] = pack_bf16(v0 - h0, v1 - h1);
                }
            }
        }

        // ---- O += P V (bf16x3) ----
#pragma unroll
        for (int kg = 0; kg < 4; kg++) {
#pragma unroll
            for (int dt = 0; dt < 4; dt++) {
                uint32_t vhf[4], vlf[4];
                uint32_t vaddr = 2u * ((kg * 16 + (lane & 15)) * ST2 + dt * 16 + (lane >> 4) * 8);
                ldsm4t(vhf, pVh + vaddr);
                ldsm4t(vlf, pVl + vaddr);
#pragma unroll
                for (int hn = 0; hn < 2; hn++) {
                    int d = dt * 2 + hn;
                    mma16816(o[d], ph[kg], vhf + hn * 2);
                    mma16816(o[d], ph[kg], vlf + hn * 2);
                    mma16816(o[d], pl_[kg], vhf + hn * 2);
                }
            }
        }
        __syncthreads();
        issue(kt + 2);
        asm volatile("cp.async.commit_group;\n");
    }

    // ---- finalize ----
    l0 += __shfl_xor_sync(0xffffffffu, l0, 1);
    l0 += __shfl_xor_sync(0xffffffffu, l0, 2);
    l1 += __shfl_xor_sync(0xffffffffu, l1, 1);
    l1 += __shfl_xor_sync(0xffffffffu, l1, 2);
    float inv0 = 1.f / l0, inv1 = 1.f / l1;
    const size_t obase = ((size_t)(b * S_) + qb * 64 + w * 16) * H_ + h * HD;
#pragma unroll
    for (int j = 0; j < 8; j++) {
        int col = j * 8 + (lane & 3) * 2;
        {
            size_t off = obase + (size_t)(lane >> 2) * H_ + col;
            float v0 = o[j][0] * inv0, v1 = o[j][1] * inv0;
            __nv_bfloat16 h0 = __float2bfloat16(v0), h1 = __float2bfloat16(v1);
            *(__nv_bfloat162*)&AOh[off] = __nv_bfloat162(h0, h1);
            *(__nv_bfloat162*)&AOl[off] = __nv_bfloat162(
                __float2bfloat16(v0 - __bfloat162float(h0)),
                __float2bfloat16(v1 - __bfloat162float(h1)));
        }
        {
            size_t off = obase + (size_t)((lane >> 2) + 8) * H_ + col;
            float v0 = o[j][2] * inv1, v1 = o[j][3] * inv1;
            __nv_bfloat16 h0 = __float2bfloat16(v0), h1 = __float2bfloat16(v1);
            *(__nv_bfloat162*)&AOh[off] = __nv_bfloat162(h0, h1);
            *(__nv_bfloat162*)&AOl[off] = __nv_bfloat162(
                __float2bfloat16(v0 - __bfloat162float(h0)),
                __float2bfloat16(v1 - __bfloat162float(h1)));
        }
    }
}

// ---------------------------------------------------------------------------
// inputs: x, position_ids(unused), mask(unused), wq, wk, wv, wo
// ---------------------------------------------------------------------------
extern "C" void kernel_launch(void* const* d_in, const int* in_sizes, int n_in,
                              void* d_out, int out_size) {
    const float* x  = (const float*)d_in[0];
    const float* wq = (const float*)d_in[3];
    const float* wk = (const float*)d_in[4];
    const float* wv = (const float*)d_in[5];
    const float* wo = (const float*)d_in[6];
    float* out = (float*)d_out;

    float *q, *k, *v;
    cudaGetSymbolAddress((void**)&q, g_q);
    cudaGetSymbolAddress((void**)&k, g_k);
    cudaGetSymbolAddress((void**)&v, g_v);
    __nv_bfloat16 *xh, *xl, *wqh, *wql, *wkh, *wkl, *wvh, *wvl, *woh, *wol;
    __nv_bfloat16 *aoh, *aol, *qh, *ql, *kh, *kl, *vh, *vl;
    cudaGetSymbolAddress((void**)&xh,  g_xh);  cudaGetSymbolAddress((void**)&xl,  g_xl);
    cudaGetSymbolAddress((void**)&wqh, g_wqh); cudaGetSymbolAddress((void**)&wql, g_wql);
    cudaGetSymbolAddress((void**)&wkh, g_wkh); cudaGetSymbolAddress((void**)&wkl, g_wkl);
    cudaGetSymbolAddress((void**)&wvh, g_wvh); cudaGetSymbolAddress((void**)&wvl, g_wvl);
    cudaGetSymbolAddress((void**)&woh, g_woh); cudaGetSymbolAddress((void**)&wol, g_wol);
    cudaGetSymbolAddress((void**)&aoh, g_aoh); cudaGetSymbolAddress((void**)&aol, g_aol);
    cudaGetSymbolAddress((void**)&qh,  g_qh);  cudaGetSymbolAddress((void**)&ql,  g_ql);
    cudaGetSymbolAddress((void**)&kh,  g_kh);  cudaGetSymbolAddress((void**)&kl,  g_kl);
    cudaGetSymbolAddress((void**)&vh,  g_vh);  cudaGetSymbolAddress((void**)&vl,  g_vl);

    cudaFuncSetAttribute(gemm_pre, cudaFuncAttributeMaxDynamicSharedMemorySize, SMEMSZ);
    cudaFuncSetAttribute(flash2,   cudaFuncAttributeMaxDynamicSharedMemorySize, FSMEM);

    cs_table_kernel<<<(S_ * 32 + 255) / 256, 256>>>();

    split_kernel<<<(MROWS * H_ / 4 + 255) / 256, 256>>>(x,  xh,  xl,  MROWS * H_);
    split_kernel<<<(H_ * H_ / 4 + 255) / 256, 256>>>(wq, wqh, wql, H_ * H_);
    split_kernel<<<(KVD * H_ / 4 + 255) / 256, 256>>>(wk, wkh, wkl, KVD * H_);
    split_kernel<<<(KVD * H_ / 4 + 255) / 256, 256>>>(wv, wvh, wvl, KVD * H_);
    split_kernel<<<(H_ * H_ / 4 + 255) / 256, 256>>>(wo, woh, wol, H_ * H_);

    dim3 gq(H_ / 128, MROWS / 128);
    dim3 gkv(KVD / 128, MROWS / 128);
    gemm_pre<<<gq, 256, SMEMSZ>>>(xh, xl, wqh, wql, q, MROWS, H_, H_);
    gemm_pre<<<gkv, 256, SMEMSZ>>>(xh, xl, wkh, wkl, k, MROWS, KVD, H_);
    gemm_pre<<<gkv, 256, SMEMSZ>>>(xh, xl, wvh, wvl, v, MROWS, KVD, H_);

    int total = MROWS * 1024 + MROWS * 256 + MROWS * 256;
    rope_split_kernel<<<(total + 255) / 256, 256>>>(q, k, v);

    dim3 ga(S_ / 64, NH, B_);
    flash2<<<ga, 128, FSMEM>>>(qh, ql, kh, kl, vh, vl, aoh, aol);

    gemm_pre<<<gq, 256, SMEMSZ>>>(aoh, aol, woh, wol, out, MROWS, H_, H_);
}

// round 8
// speedup vs baseline: 1.0079x; 1.0079x over previous
#include <cuda_runtime.h>
#include <cuda_bf16.h>
#include <math.h>
#include <stdint.h>

// Problem constants
#define B_    2
#define S_    2048
#define H_    2048
#define NH    32
#define NKV   8
#define HD    64
#define KVD   512           // NKV * HD
#define MROWS 4096          // B_ * S_

// fp32 scratch
__device__ float g_q [MROWS * H_];
__device__ float g_k [MROWS * KVD];
__device__ float g_v [MROWS * KVD];
__device__ float2 g_cs[S_ * 32];

// bf16 hi/lo splits
__device__ __nv_bfloat16 g_xh [MROWS * H_],  g_xl [MROWS * H_];
__device__ __nv_bfloat16 g_wqh[H_ * H_],     g_wql[H_ * H_];
__device__ __nv_bfloat16 g_wkh[KVD * H_],    g_wkl[KVD * H_];
__device__ __nv_bfloat16 g_wvh[KVD * H_],    g_wvl[KVD * H_];
__device__ __nv_bfloat16 g_woh[H_ * H_],     g_wol[H_ * H_];
__device__ __nv_bfloat16 g_aoh[MROWS * H_],  g_aol[MROWS * H_];
__device__ __nv_bfloat16 g_qh[MROWS * H_],   g_ql[MROWS * H_];
__device__ __nv_bfloat16 g_kh[MROWS * KVD],  g_kl[MROWS * KVD];
__device__ __nv_bfloat16 g_vh[MROWS * KVD],  g_vl[MROWS * KVD];

// ---------------------------------------------------------------------------
// helpers
// ---------------------------------------------------------------------------
__device__ __forceinline__ void mma16816(float* c, const uint32_t* a, const uint32_t* b) {
    asm volatile(
        "mma.sync.aligned.m16n8k16.row.col.f32.bf16.bf16.f32 "
        "{%0,%1,%2,%3}, {%4,%5,%6,%7}, {%8,%9}, {%0,%1,%2,%3};\n"
        : "+f"(c[0]), "+f"(c[1]), "+f"(c[2]), "+f"(c[3])
        : "r"(a[0]), "r"(a[1]), "r"(a[2]), "r"(a[3]), "r"(b[0]), "r"(b[1]));
}
__device__ __forceinline__ void ldsm4(uint32_t* r, uint32_t addr) {
    asm volatile("ldmatrix.sync.aligned.m8n8.x4.shared.b16 {%0,%1,%2,%3}, [%4];\n"
                 : "=r"(r[0]), "=r"(r[1]), "=r"(r[2]), "=r"(r[3]) : "r"(addr));
}
__device__ __forceinline__ void ldsm4t(uint32_t* r, uint32_t addr) {
    asm volatile("ldmatrix.sync.aligned.m8n8.x4.trans.shared.b16 {%0,%1,%2,%3}, [%4];\n"
                 : "=r"(r[0]), "=r"(r[1]), "=r"(r[2]), "=r"(r[3]) : "r"(addr));
}
__device__ __forceinline__ uint32_t pack_bf16(float a, float b) {
    __nv_bfloat162 t = __floats2bfloat162_rn(a, b);
    return *(uint32_t*)&t;
}
__device__ __forceinline__ void cp16(uint32_t dst, const void* src) {
    asm volatile("cp.async.cg.shared.global [%0], [%1], 16;\n" :: "r"(dst), "l"(src));
}

// ---------------------------------------------------------------------------
// hi/lo split: src fp32 -> h,l bf16
// ---------------------------------------------------------------------------
__global__ void split_kernel(const float* __restrict__ src,
                             __nv_bfloat16* __restrict__ h,
                             __nv_bfloat16* __restrict__ l, int n) {
    int i = (blockIdx.x * blockDim.x + threadIdx.x) * 4;
    if (i >= n) return;
    float4 v = *(const float4*)(src + i);
    __nv_bfloat16 h0 = __float2bfloat16(v.x), h1 = __float2bfloat16(v.y);
    __nv_bfloat16 h2 = __float2bfloat16(v.z), h3 = __float2bfloat16(v.w);
    *(__nv_bfloat162*)&h[i]     = __nv_bfloat162(h0, h1);
    *(__nv_bfloat162*)&h[i + 2] = __nv_bfloat162(h2, h3);
    *(__nv_bfloat162*)&l[i] = __nv_bfloat162(
        __float2bfloat16(v.x - __bfloat162float(h0)),
        __float2bfloat16(v.y - __bfloat162float(h1)));
    *(__nv_bfloat162*)&l[i + 2] = __nv_bfloat162(
        __float2bfloat16(v.z - __bfloat162float(h2)),
        __float2bfloat16(v.w - __bfloat162float(h3)));
}

// ---------------------------------------------------------------------------
// Pipelined bf16x3 GEMM: C[M,N] = (Ah+Al)[M,K] @ (Bh+Bl)[N,K]^T
// 128x128 tile, BK=32, 3-stage cp.async pipeline, 256 threads, warp tile 64x32.
// Accumulator-RAW-free schedule: three passes per k-slice, each acc touched
// once per 16-mma sweep.
// ---------------------------------------------------------------------------
#define ST 40                      // smem row stride (bf16 elems)
#define ABYTES (128 * ST * 2)      // 10240 per array
#define STAGEB (4 * ABYTES)        // 40960 per stage
#define SMEMSZ (3 * STAGEB)        // 122880

__global__ void __launch_bounds__(256)
gemm_pre(const __nv_bfloat16* __restrict__ Ah, const __nv_bfloat16* __restrict__ Al,
         const __nv_bfloat16* __restrict__ Bh, const __nv_bfloat16* __restrict__ Bl,
         float* __restrict__ C, int M, int N, int K) {
    extern __shared__ char dsm[];
    const uint32_t smem0 = (uint32_t)__cvta_generic_to_shared(dsm);

    const int t    = threadIdx.x;
    const int lane = t & 31;
    const int w    = t >> 5;
    const int wm   = (w & 1) * 64;
    const int wn   = (w >> 1) * 32;
    const int m0   = blockIdx.y * 128;
    const int n0   = blockIdx.x * 128;

    const int g = lane >> 3, r = lane & 7;
    const int a_moff = (g & 1) * 8 + r;
    const int a_koff = (g >> 1) * 8;
    const int b_noff = (g >> 1) * 8 + r;
    const int b_koff = (g & 1) * 8;

    const int id0 = t, id1 = t + 256;
    const int r0 = id0 >> 2, c0 = (id0 & 3) * 8;
    const int r1 = id1 >> 2, c1 = (id1 & 3) * 8;

    const int nkt = K >> 5;

    auto issue = [&](int kt) {
        int s = kt % 3;
        int k0 = kt << 5;
        uint32_t base = smem0 + s * STAGEB;
        uint32_t d0 = base + (r0 * ST + c0) * 2;
        uint32_t d1 = base + (r1 * ST + c1) * 2;
        size_t ao0 = (size_t)(m0 + r0) * K + k0 + c0;
        size_t ao1 = (size_t)(m0 + r1) * K + k0 + c1;
        size_t bo0 = (size_t)(n0 + r0) * K + k0 + c0;
        size_t bo1 = (size_t)(n0 + r1) * K + k0 + c1;
        cp16(d0,              Ah + ao0); cp16(d1,              Ah + ao1);
        cp16(d0 + ABYTES,     Al + ao0); cp16(d1 + ABYTES,     Al + ao1);
        cp16(d0 + 2 * ABYTES, Bh + bo0); cp16(d1 + 2 * ABYTES, Bh + bo1);
        cp16(d0 + 3 * ABYTES, Bl + bo0); cp16(d1 + 3 * ABYTES, Bl + bo1);
    };

    float acc[4][4][4];
#pragma unroll
    for (int i = 0; i < 4; i++)
#pragma unroll
        for (int j = 0; j < 4; j++)
#pragma unroll
            for (int e = 0; e < 4; e++) acc[i][j][e] = 0.f;

    issue(0); asm volatile("cp.async.commit_group;\n");
    issue(1); asm volatile("cp.async.commit_group;\n");

    for (int kt = 0; kt < nkt; kt++) {
        asm volatile("cp.async.wait_group 1;\n");
        __syncthreads();
        if (kt + 2 < nkt) issue(kt + 2);
        asm volatile("cp.async.commit_group;\n");

        const uint32_t base = smem0 + (kt % 3) * STAGEB;
        const uint32_t sAh = base, sAl = base + ABYTES;
        const uint32_t sBh = base + 2 * ABYTES, sBl = base + 3 * ABYTES;

#pragma unroll
        for (int ks = 0; ks < 2; ks++) {
            const int kk = ks * 16;
            uint32_t afh[4][4], afl[4][4], b1[2][4], b2[2][4];
#pragma unroll
            for (int mi = 0; mi < 4; mi++)
                ldsm4(afh[mi], sAh + 2u * ((wm + mi * 16 + a_moff) * ST + kk + a_koff));
#pragma unroll
            for (int nb = 0; nb < 2; nb++) {
                ldsm4(b1[nb], sBh + 2u * ((wn + nb * 16 + b_noff) * ST + kk + b_koff));
                ldsm4(b2[nb], sBl + 2u * ((wn + nb * 16 + b_noff) * ST + kk + b_koff));
            }
#pragma unroll
            for (int mi = 0; mi < 4; mi++)
                ldsm4(afl[mi], sAl + 2u * ((wm + mi * 16 + a_moff) * ST + kk + a_koff));
            // pass 1: A1*B1  (16 mmas, all distinct accumulators)
#pragma unroll
            for (int mi = 0; mi < 4; mi++)
#pragma unroll
                for (int ni = 0; ni < 4; ni++)
                    mma16816(acc[mi][ni], afh[mi], &b1[ni >> 1][(ni & 1) * 2]);
            // pass 2: A1*B2
#pragma unroll
            for (int mi = 0; mi < 4; mi++)
#pragma unroll
                for (int ni = 0; ni < 4; ni++)
                    mma16816(acc[mi][ni], afh[mi], &b2[ni >> 1][(ni & 1) * 2]);
            // pass 3: A2*B1
#pragma unroll
            for (int mi = 0; mi < 4; mi++)
#pragma unroll
                for (int ni = 0; ni < 4; ni++)
                    mma16816(acc[mi][ni], afl[mi], &b1[ni >> 1][(ni & 1) * 2]);
        }
        __syncthreads();
    }

#pragma unroll
    for (int mi = 0; mi < 4; mi++) {
        int row = m0 + wm + mi * 16 + (lane >> 2);
#pragma unroll
        for (int ni = 0; ni < 4; ni++) {
            int col = n0 + wn + ni * 8 + (lane & 3) * 2;
            *(float2*)&C[(size_t)row * N + col]       = make_float2(acc[mi][ni][0], acc[mi][ni][1]);
            *(float2*)&C[(size_t)(row + 8) * N + col] = make_float2(acc[mi][ni][2], acc[mi][ni][3]);
        }
    }
}

// ---------------------------------------------------------------------------
// cos/sin table
// ---------------------------------------------------------------------------
__global__ void cs_table_kernel() {
    int i = blockIdx.x * blockDim.x + threadIdx.x;
    if (i >= S_ * 32) return;
    int pos = i >> 5, p = i & 31;
    double inv = exp(-((double)(2 * p) / 64.0) * log(10000.0));
    double ang = (double)pos * inv;
    g_cs[i] = make_float2((float)cos(ang), (float)sin(ang));
}

// ---------------------------------------------------------------------------
// Fused RoPE (Q,K) + hi/lo split of Q, K, V
// ---------------------------------------------------------------------------
__global__ void rope_split_kernel(const float* __restrict__ q,
                                  const float* __restrict__ k,
                                  const float* __restrict__ v) {
    const int NQ = MROWS * 1024;
    const int NK = MROWS * 256;
    const int NV = MROWS * 256;
    int idx = blockIdx.x * blockDim.x + threadIdx.x;
    if (idx >= NQ + NK + NV) return;

    if (idx < NQ + NK) {
        const float* src; __nv_bfloat16 *dh, *dl;
        int row, p, head, rowstride;
        if (idx < NQ) {
            row = idx >> 10; int rem = idx & 1023;
            head = rem >> 5; p = rem & 31; rowstride = H_;
            src = q; dh = g_qh; dl = g_ql;
        } else {
            int i2 = idx - NQ;
            row = i2 >> 8; int rem = i2 & 255;
            head = rem >> 5; p = rem & 31; rowstride = KVD;
            src = k; dh = g_kh; dl = g_kl;
        }
        size_t base = (size_t)row * rowstride + head * HD;
        int pos = row & (S_ - 1);
        float2 cs = g_cs[pos * 32 + p];
        float x0 = src[base + p], x1 = src[base + p + 32];
        float y0 = x0 * cs.x - x1 * cs.y;
        float y1 = x1 * cs.x + x0 * cs.y;
        __nv_bfloat16 h0 = __float2bfloat16(y0);
        __nv_bfloat16 h1 = __float2bfloat16(y1);
        dh[base + p]      = h0;
        dh[base + p + 32] = h1;
        dl[base + p]      = __float2bfloat16(y0 - __bfloat162float(h0));
        dl[base + p + 32] = __float2bfloat16(y1 - __bfloat162float(h1));
    } else {
        int i2 = idx - NQ - NK;
        size_t base = (size_t)(i2 >> 8) * KVD + (i2 & 255) * 2;
        float x0 = v[base], x1 = v[base + 1];
        __nv_bfloat16 h0 = __float2bfloat16(x0);
        __nv_bfloat16 h1 = __float2bfloat16(x1);
        g_vh[base]     = h0;
        g_vh[base + 1] = h1;
        g_vl[base]     = __float2bfloat16(x0 - __bfloat162float(h0));
        g_vl[base + 1] = __float2bfloat16(x1 - __bfloat162float(h1));
    }
}

// ---------------------------------------------------------------------------
// Tensor-core causal flash attention, 2-stage cp.async pipelined K/V tiles.
// Accumulator-RAW-free mma schedule (3 passes per fragment group).
// ---------------------------------------------------------------------------
#define ST2 72
#define FA  (64 * ST2 * 2)
#define FSTAGE (4 * FA)
#define FSMEM  (2 * FSTAGE)

__global__ void __launch_bounds__(128)
flash2(const __nv_bfloat16* __restrict__ Qh, const __nv_bfloat16* __restrict__ Ql,
       const __nv_bfloat16* __restrict__ Kh, const __nv_bfloat16* __restrict__ Kl,
       const __nv_bfloat16* __restrict__ Vh, const __nv_bfloat16* __restrict__ Vl,
       __nv_bfloat16* __restrict__ AOh, __nv_bfloat16* __restrict__ AOl) {
    extern __shared__ char fsm[];
    const uint32_t smem0 = (uint32_t)__cvta_generic_to_shared(fsm);

    const int t = threadIdx.x, lane = t & 31, w = t >> 5;
    const int qb = blockIdx.x, h = blockIdx.y, b = blockIdx.z, kvh = h >> 2;
    const int g = lane >> 3, r = lane & 7;
    const int a_row = (g & 1) * 8 + r, a_k = (g >> 1) * 8;
    const int b_row = (g >> 1) * 8 + r, b_k = (g & 1) * 8;

    const int ntiles = qb + 1;
    const size_t bS = (size_t)(b * S_);

    {
        __nv_bfloat16* s0h = (__nv_bfloat16*)(fsm);
        __nv_bfloat16* s0l = (__nv_bfloat16*)(fsm + FA);
        const size_t qbase = (bS + qb * 64) * H_ + h * HD;
#pragma unroll
        for (int i = 0; i < 4; i++) {
            int idx = t + i * 128;
            int row = idx >> 3, c = (idx & 7) * 8;
            *(uint4*)&s0h[row * ST2 + c] = *(const uint4*)(Qh + qbase + (size_t)row * H_ + c);
            *(uint4*)&s0l[row * ST2 + c] = *(const uint4*)(Ql + qbase + (size_t)row * H_ + c);
        }
    }
    __syncthreads();
    uint32_t qh[4][4], ql[4][4];
#pragma unroll
    for (int ks = 0; ks < 4; ks++) {
        ldsm4(qh[ks], smem0 + 2u * ((w * 16 + a_row) * ST2 + ks * 16 + a_k));
        ldsm4(ql[ks], smem0 + FA + 2u * ((w * 16 + a_row) * ST2 + ks * 16 + a_k));
    }
    __syncthreads();

    auto issue = [&](int kt) {
        if (kt >= ntiles) return;
        uint32_t base = smem0 + (kt & 1) * FSTAGE;
        const size_t kb = (bS + kt * 64) * KVD + kvh * HD;
#pragma unroll
        for (int i = 0; i < 4; i++) {
            int chunk = t + i * 128;
            int row = chunk >> 3, col = (chunk & 7) * 8;
            size_t go = kb + (size_t)row * KVD + col;
            uint32_t so = base + (row * ST2 + col) * 2;
            cp16(so,          Kh + go);
            cp16(so + FA,     Kl + go);
            cp16(so + 2 * FA, Vh + go);
            cp16(so + 3 * FA, Vl + go);
        }
    };

    issue(0); asm volatile("cp.async.commit_group;\n");
    issue(1); asm volatile("cp.async.commit_group;\n");

    float o[8][4];
#pragma unroll
    for (int j = 0; j < 8; j++)
#pragma unroll
        for (int e = 0; e < 4; e++) o[j][e] = 0.f;
    float m0 = -3.0e38f, m1 = -3.0e38f, l0 = 0.f, l1 = 0.f;
    const int qr0 = qb * 64 + w * 16 + (lane >> 2);
    const int qr1 = qr0 + 8;

    for (int kt = 0; kt < ntiles; kt++) {
        asm volatile("cp.async.wait_group 1;\n");
        __syncthreads();

        const uint32_t base = smem0 + (kt & 1) * FSTAGE;
        const uint32_t pKh = base, pKl = base + FA;
        const uint32_t pVh = base + 2 * FA, pVl = base + 3 * FA;
        const int k0 = kt * 64;

        // ---- S = Q K^T (bf16x3), RAW-free schedule ----
        float s[8][4];
#pragma unroll
        for (int j = 0; j < 8; j++)
#pragma unroll
            for (int e = 0; e < 4; e++) s[j][e] = 0.f;
#pragma unroll
        for (int ks = 0; ks < 4; ks++) {
            uint32_t bh[4][4], bl[4][4];
#pragma unroll
            for (int nb = 0; nb < 4; nb++) {
                ldsm4(bh[nb], pKh + 2u * ((nb * 16 + b_row) * ST2 + ks * 16 + b_k));
                ldsm4(bl[nb], pKl + 2u * ((nb * 16 + b_row) * ST2 + ks * 16 + b_k));
            }
            // pass 1: Qh * Kh   (8 distinct accumulators)
#pragma unroll
            for (int nb = 0; nb < 4; nb++)
#pragma unroll
                for (int hn = 0; hn < 2; hn++)
                    mma16816(s[nb * 2 + hn], qh[ks], bh[nb] + hn * 2);
            // pass 2: Qh * Kl
#pragma unroll
            for (int nb = 0; nb < 4; nb++)
#pragma unroll
                for (int hn = 0; hn < 2; hn++)
                    mma16816(s[nb * 2 + hn], qh[ks], bl[nb] + hn * 2);
            // pass 3: Ql * Kh
#pragma unroll
            for (int nb = 0; nb < 4; nb++)
#pragma unroll
                for (int hn = 0; hn < 2; hn++)
                    mma16816(s[nb * 2 + hn], ql[ks], bh[nb] + hn * 2);
        }

        // ---- scale + causal mask + online softmax ----
        const bool diag = (kt == ntiles - 1);
        float mx0 = -3.0e38f, mx1 = -3.0e38f;
#pragma unroll
        for (int j = 0; j < 8; j++) {
            int colb = k0 + j * 8 + (lane & 3) * 2;
#pragma unroll
            for (int e = 0; e < 4; e++) {
                float val = s[j][e] * 0.125f;
                if (diag) {
                    int col = colb + (e & 1);
                    int qr  = (e < 2) ? qr0 : qr1;
                    if (col > qr) val = -1.0e9f;
                }
                s[j][e] = val;
                if (e < 2) mx0 = fmaxf(mx0, val); else mx1 = fmaxf(mx1, val);
            }
        }
        mx0 = fmaxf(mx0, __shfl_xor_sync(0xffffffffu, mx0, 1));
        mx0 = fmaxf(mx0, __shfl_xor_sync(0xffffffffu, mx0, 2));
        mx1 = fmaxf(mx1, __shfl_xor_sync(0xffffffffu, mx1, 1));
        mx1 = fmaxf(mx1, __shfl_xor_sync(0xffffffffu, mx1, 2));
        float nm0 = fmaxf(m0, mx0), nm1 = fmaxf(m1, mx1);
        float c0 = __expf(m0 - nm0), c1 = __expf(m1 - nm1);
        l0 *= c0; l1 *= c1;
#pragma unroll
        for (int j = 0; j < 8; j++) {
            o[j][0] *= c0; o[j][1] *= c0;
            o[j][2] *= c1; o[j][3] *= c1;
        }
        m0 = nm0; m1 = nm1;
        float rs0 = 0.f, rs1 = 0.f;
#pragma unroll
        for (int j = 0; j < 8; j++) {
#pragma unroll
            for (int e = 0; e < 4; e++) {
                float p = __expf(s[j][e] - ((e < 2) ? m0 : m1));
                s[j][e] = p;
                if (e < 2) rs0 += p; else rs1 += p;
            }
        }
        l0 += rs0; l1 += rs1;

        // ---- P fragments (hi/lo) ----
        uint32_t ph[4][4], pl_[4][4];
#pragma unroll
        for (int kg = 0; kg < 4; kg++) {
#pragma unroll
            for (int q2 = 0; q2 < 2; q2++) {
                int j = 2 * kg + q2;
#pragma unroll
                for (int half = 0; half < 2; half++) {
                    float v0 = s[j][half * 2], v1 = s[j][half * 2 + 1];
                    float h0 = __bfloat162float(__float2bfloat16(v0));
                    float h1 = __bfloat162float(__float2bfloat16(v1));
                    ph[kg][q2 * 2 + half]  = pack_bf16(h0, h1);
                    pl_[kg][q2 * 2 + half] = pack_bf16(v0 - h0, v1 - h1);
                }
            }
        }

        // ---- O += P V (bf16x3), RAW-free schedule ----
#pragma unroll
        for (int kg = 0; kg < 4; kg++) {
            uint32_t vhf[4][4], vlf[4][4];
#pragma unroll
            for (int dt = 0; dt < 4; dt++) {
                uint32_t vaddr = 2u * ((kg * 16 + (lane & 15)) * ST2 + dt * 16 + (lane >> 4) * 8);
                ldsm4t(vhf[dt], pVh + vaddr);
                ldsm4t(vlf[dt], pVl + vaddr);
            }
            // pass 1: Ph * Vh  (8 distinct accumulators)
#pragma unroll
            for (int dt = 0; dt < 4; dt++)
#pragma unroll
                for (int hn = 0; hn < 2; hn++)
                    mma16816(o[dt * 2 + hn], ph[kg], vhf[dt] + hn * 2);
            // pass 2: Ph * Vl
#pragma unroll
            for (int dt = 0; dt < 4; dt++)
#pragma unroll
                for (int hn = 0; hn < 2; hn++)
                    mma16816(o[dt * 2 + hn], ph[kg], vlf[dt] + hn * 2);
            // pass 3: Pl * Vh
#pragma unroll
            for (int dt = 0; dt < 4; dt++)
#pragma unroll
                for (int hn = 0; hn < 2; hn++)
                    mma16816(o[dt * 2 + hn], pl_[kg], vhf[dt] + hn * 2);
        }
        __syncthreads();
        issue(kt + 2);
        asm volatile("cp.async.commit_group;\n");
    }

    l0 += __shfl_xor_sync(0xffffffffu, l0, 1);
    l0 += __shfl_xor_sync(0xffffffffu, l0, 2);
    l1 += __shfl_xor_sync(0xffffffffu, l1, 1);
    l1 += __shfl_xor_sync(0xffffffffu, l1, 2);
    float inv0 = 1.f / l0, inv1 = 1.f / l1;
    const size_t obase = ((size_t)(b * S_) + qb * 64 + w * 16) * H_ + h * HD;
#pragma unroll
    for (int j = 0; j < 8; j++) {
        int col = j * 8 + (lane & 3) * 2;
        {
            size_t off = obase + (size_t)(lane >> 2) * H_ + col;
            float v0 = o[j][0] * inv0, v1 = o[j][1] * inv0;
            __nv_bfloat16 h0 = __float2bfloat16(v0), h1 = __float2bfloat16(v1);
            *(__nv_bfloat162*)&AOh[off] = __nv_bfloat162(h0, h1);
            *(__nv_bfloat162*)&AOl[off] = __nv_bfloat162(
                __float2bfloat16(v0 - __bfloat162float(h0)),
                __float2bfloat16(v1 - __bfloat162float(h1)));
        }
        {
            size_t off = obase + (size_t)((lane >> 2) + 8) * H_ + col;
            float v0 = o[j][2] * inv1, v1 = o[j][3] * inv1;
            __nv_bfloat16 h0 = __float2bfloat16(v0), h1 = __float2bfloat16(v1);
            *(__nv_bfloat162*)&AOh[off] = __nv_bfloat162(h0, h1);
            *(__nv_bfloat162*)&AOl[off] = __nv_bfloat162(
                __float2bfloat16(v0 - __bfloat162float(h0)),
                __float2bfloat16(v1 - __bfloat162float(h1)));
        }
    }
}

// ---------------------------------------------------------------------------
// inputs: x, position_ids(unused), mask(unused), wq, wk, wv, wo
// ---------------------------------------------------------------------------
extern "C" void kernel_launch(void* const* d_in, const int* in_sizes, int n_in,
                              void* d_out, int out_size) {
    const float* x  = (const float*)d_in[0];
    const float* wq = (const float*)d_in[3];
    const float* wk = (const float*)d_in[4];
    const float* wv = (const float*)d_in[5];
    const float* wo = (const float*)d_in[6];
    float* out = (float*)d_out;

    float *q, *k, *v;
    cudaGetSymbolAddress((void**)&q, g_q);
    cudaGetSymbolAddress((void**)&k, g_k);
    cudaGetSymbolAddress((void**)&v, g_v);
    __nv_bfloat16 *xh, *xl, *wqh, *wql, *wkh, *wkl, *wvh, *wvl, *woh, *wol;
    __nv_bfloat16 *aoh, *aol, *qh, *ql, *kh, *kl, *vh, *vl;
    cudaGetSymbolAddress((void**)&xh,  g_xh);  cudaGetSymbolAddress((void**)&xl,  g_xl);
    cudaGetSymbolAddress((void**)&wqh, g_wqh); cudaGetSymbolAddress((void**)&wql, g_wql);
    cudaGetSymbolAddress((void**)&wkh, g_wkh); cudaGetSymbolAddress((void**)&wkl, g_wkl);
    cudaGetSymbolAddress((void**)&wvh, g_wvh); cudaGetSymbolAddress((void**)&wvl, g_wvl);
    cudaGetSymbolAddress((void**)&woh, g_woh); cudaGetSymbolAddress((void**)&wol, g_wol);
    cudaGetSymbolAddress((void**)&aoh, g_aoh); cudaGetSymbolAddress((void**)&aol, g_aol);
    cudaGetSymbolAddress((void**)&qh,  g_qh);  cudaGetSymbolAddress((void**)&ql,  g_ql);
    cudaGetSymbolAddress((void**)&kh,  g_kh);  cudaGetSymbolAddress((void**)&kl,  g_kl);
    cudaGetSymbolAddress((void**)&vh,  g_vh);  cudaGetSymbolAddress((void**)&vl,  g_vl);

    cudaFuncSetAttribute(gemm_pre, cudaFuncAttributeMaxDynamicSharedMemorySize, SMEMSZ);
    cudaFuncSetAttribute(flash2,   cudaFuncAttributeMaxDynamicSharedMemorySize, FSMEM);

    cs_table_kernel<<<(S_ * 32 + 255) / 256, 256>>>();

    split_kernel<<<(MROWS * H_ / 4 + 255) / 256, 256>>>(x,  xh,  xl,  MROWS * H_);
    split_kernel<<<(H_ * H_ / 4 + 255) / 256, 256>>>(wq, wqh, wql, H_ * H_);
    split_kernel<<<(KVD * H_ / 4 + 255) / 256, 256>>>(wk, wkh, wkl, KVD * H_);
    split_kernel<<<(KVD * H_ / 4 + 255) / 256, 256>>>(wv, wvh, wvl, KVD * H_);
    split_kernel<<<(H_ * H_ / 4 + 255) / 256, 256>>>(wo, woh, wol, H_ * H_);

    dim3 gq(H_ / 128, MROWS / 128);
    dim3 gkv(KVD / 128, MROWS / 128);
    gemm_pre<<<gq, 256, SMEMSZ>>>(xh, xl, wqh, wql, q, MROWS, H_, H_);
    gemm_pre<<<gkv, 256, SMEMSZ>>>(xh, xl, wkh, wkl, k, MROWS, KVD, H_);
    gemm_pre<<<gkv, 256, SMEMSZ>>>(xh, xl, wvh, wvl, v, MROWS, KVD, H_);

    int total = MROWS * 1024 + MROWS * 256 + MROWS * 256;
    rope_split_kernel<<<(total + 255) / 256, 256>>>(q, k, v);

    dim3 ga(S_ / 64, NH, B_);
    flash2<<<ga, 128, FSMEM>>>(qh, ql, kh, kl, vh, vl, aoh, aol);

    gemm_pre<<<gq, 256, SMEMSZ>>>(aoh, aol, woh, wol, out, MROWS, H_, H_);
}

// round 9
// speedup vs baseline: 1.5170x; 1.5052x over previous
#include <cuda_runtime.h>
#include <cuda_fp16.h>
#include <math.h>
#include <stdint.h>

// Problem constants
#define B_    2
#define S_    2048
#define H_    2048
#define NH    32
#define NKV   8
#define HD    64
#define KVD   512           // NKV * HD
#define MROWS 4096          // B_ * S_

// fp32 scratch
__device__ float g_q [MROWS * H_];
__device__ float g_k [MROWS * KVD];
__device__ float g_v [MROWS * KVD];
__device__ float2 g_cs[S_ * 32];

// fp16 operands: A-side single, B-side hi/lo split
__device__ __half g_xh [MROWS * H_];
__device__ __half g_wqh[H_ * H_],    g_wql[H_ * H_];
__device__ __half g_wkh[KVD * H_],   g_wkl[KVD * H_];
__device__ __half g_wvh[KVD * H_],   g_wvl[KVD * H_];
__device__ __half g_woh[H_ * H_],    g_wol[H_ * H_];
__device__ __half g_aoh[MROWS * H_];
__device__ __half g_qh [MROWS * H_];
__device__ __half g_kh [MROWS * KVD], g_kl[MROWS * KVD];
__device__ __half g_vh [MROWS * KVD], g_vl[MROWS * KVD];

// ---------------------------------------------------------------------------
// helpers
// ---------------------------------------------------------------------------
__device__ __forceinline__ void mma16816(float* c, const uint32_t* a, const uint32_t* b) {
    asm volatile(
        "mma.sync.aligned.m16n8k16.row.col.f32.f16.f16.f32 "
        "{%0,%1,%2,%3}, {%4,%5,%6,%7}, {%8,%9}, {%0,%1,%2,%3};\n"
        : "+f"(c[0]), "+f"(c[1]), "+f"(c[2]), "+f"(c[3])
        : "r"(a[0]), "r"(a[1]), "r"(a[2]), "r"(a[3]), "r"(b[0]), "r"(b[1]));
}
__device__ __forceinline__ void ldsm4(uint32_t* r, uint32_t addr) {
    asm volatile("ldmatrix.sync.aligned.m8n8.x4.shared.b16 {%0,%1,%2,%3}, [%4];\n"
                 : "=r"(r[0]), "=r"(r[1]), "=r"(r[2]), "=r"(r[3]) : "r"(addr));
}
__device__ __forceinline__ void ldsm4t(uint32_t* r, uint32_t addr) {
    asm volatile("ldmatrix.sync.aligned.m8n8.x4.trans.shared.b16 {%0,%1,%2,%3}, [%4];\n"
                 : "=r"(r[0]), "=r"(r[1]), "=r"(r[2]), "=r"(r[3]) : "r"(addr));
}
__device__ __forceinline__ uint32_t pack_h(float a, float b) {
    __half2 t = __floats2half2_rn(a, b);
    return *(uint32_t*)&t;
}
__device__ __forceinline__ void cp16(uint32_t dst, const void* src) {
    asm volatile("cp.async.cg.shared.global [%0], [%1], 16;\n" :: "r"(dst), "l"(src));
}

// ---------------------------------------------------------------------------
// fp32 -> fp16 convert (A-side) and hi/lo split (B-side)
// ---------------------------------------------------------------------------
__global__ void convert_h(const float* __restrict__ src, __half* __restrict__ h, int n) {
    int i = (blockIdx.x * blockDim.x + threadIdx.x) * 4;
    if (i >= n) return;
    float4 v = *(const float4*)(src + i);
    *(__half2*)&h[i]     = __floats2half2_rn(v.x, v.y);
    *(__half2*)&h[i + 2] = __floats2half2_rn(v.z, v.w);
}

__global__ void split_hl(const float* __restrict__ src,
                         __half* __restrict__ h, __half* __restrict__ l, int n) {
    int i = (blockIdx.x * blockDim.x + threadIdx.x) * 4;
    if (i >= n) return;
    float4 v = *(const float4*)(src + i);
    __half h0 = __float2half_rn(v.x), h1 = __float2half_rn(v.y);
    __half h2 = __float2half_rn(v.z), h3 = __float2half_rn(v.w);
    *(__half2*)&h[i]     = __half2(h0, h1);
    *(__half2*)&h[i + 2] = __half2(h2, h3);
    *(__half2*)&l[i] = __floats2half2_rn(v.x - __half2float(h0), v.y - __half2float(h1));
    *(__half2*)&l[i + 2] = __floats2half2_rn(v.z - __half2float(h2), v.w - __half2float(h3));
}

// ---------------------------------------------------------------------------
// Pipelined fp16x2 GEMM: C[M,N] = A[M,K] @ (Bh+Bl)[N,K]^T
// 128x128 tile, BK=32, 3-stage cp.async, 256 threads, warp tile 64x32.
// 2 mma passes per k-slice (A*Bh, A*Bl), each acc touched once per 16-mma sweep.
// ---------------------------------------------------------------------------
#define ST 40                      // smem row stride (fp16 elems)
#define ABYTES (128 * ST * 2)      // 10240 per array
#define STAGEB (3 * ABYTES)        // A, Bh, Bl = 30720 per stage
#define SMEMSZ (3 * STAGEB)        // 92160

__global__ void __launch_bounds__(256)
gemm_pre(const __half* __restrict__ A,
         const __half* __restrict__ Bh, const __half* __restrict__ Bl,
         float* __restrict__ C, int M, int N, int K) {
    extern __shared__ char dsm[];
    const uint32_t smem0 = (uint32_t)__cvta_generic_to_shared(dsm);

    const int t    = threadIdx.x;
    const int lane = t & 31;
    const int w    = t >> 5;
    const int wm   = (w & 1) * 64;
    const int wn   = (w >> 1) * 32;
    const int m0   = blockIdx.y * 128;
    const int n0   = blockIdx.x * 128;

    const int g = lane >> 3, r = lane & 7;
    const int a_moff = (g & 1) * 8 + r;
    const int a_koff = (g >> 1) * 8;
    const int b_noff = (g >> 1) * 8 + r;
    const int b_koff = (g & 1) * 8;

    const int r0 = t >> 2, c0 = (t & 3) * 8;
    const int r1 = (t + 256) >> 2, c1 = ((t + 256) & 3) * 8;

    const int nkt = K >> 5;

    auto issue = [&](int kt) {
        int k0 = kt << 5;
        uint32_t base = smem0 + (kt % 3) * STAGEB;
        uint32_t d0 = base + (r0 * ST + c0) * 2;
        uint32_t d1 = base + (r1 * ST + c1) * 2;
        size_t ao0 = (size_t)(m0 + r0) * K + k0 + c0;
        size_t ao1 = (size_t)(m0 + r1) * K + k0 + c1;
        size_t bo0 = (size_t)(n0 + r0) * K + k0 + c0;
        size_t bo1 = (size_t)(n0 + r1) * K + k0 + c1;
        cp16(d0,              A  + ao0); cp16(d1,              A  + ao1);
        cp16(d0 + ABYTES,     Bh + bo0); cp16(d1 + ABYTES,     Bh + bo1);
        cp16(d0 + 2 * ABYTES, Bl + bo0); cp16(d1 + 2 * ABYTES, Bl + bo1);
    };

    float acc[4][4][4];
#pragma unroll
    for (int i = 0; i < 4; i++)
#pragma unroll
        for (int j = 0; j < 4; j++)
#pragma unroll
            for (int e = 0; e < 4; e++) acc[i][j][e] = 0.f;

    issue(0); asm volatile("cp.async.commit_group;\n");
    issue(1); asm volatile("cp.async.commit_group;\n");

    for (int kt = 0; kt < nkt; kt++) {
        asm volatile("cp.async.wait_group 1;\n");
        __syncthreads();
        if (kt + 2 < nkt) issue(kt + 2);
        asm volatile("cp.async.commit_group;\n");

        const uint32_t base = smem0 + (kt % 3) * STAGEB;
        const uint32_t sA  = base;
        const uint32_t sBh = base + ABYTES;
        const uint32_t sBl = base + 2 * ABYTES;

#pragma unroll
        for (int ks = 0; ks < 2; ks++) {
            const int kk = ks * 16;
            uint32_t af[4][4], b1[2][4], b2[2][4];
#pragma unroll
            for (int mi = 0; mi < 4; mi++)
                ldsm4(af[mi], sA + 2u * ((wm + mi * 16 + a_moff) * ST + kk + a_koff));
#pragma unroll
            for (int nb = 0; nb < 2; nb++) {
                ldsm4(b1[nb], sBh + 2u * ((wn + nb * 16 + b_noff) * ST + kk + b_koff));
                ldsm4(b2[nb], sBl + 2u * ((wn + nb * 16 + b_noff) * ST + kk + b_koff));
            }
            // pass 1: A * Bh  (16 distinct accumulators)
#pragma unroll
            for (int mi = 0; mi < 4; mi++)
#pragma unroll
                for (int ni = 0; ni < 4; ni++)
                    mma16816(acc[mi][ni], af[mi], &b1[ni >> 1][(ni & 1) * 2]);
            // pass 2: A * Bl
#pragma unroll
            for (int mi = 0; mi < 4; mi++)
#pragma unroll
                for (int ni = 0; ni < 4; ni++)
                    mma16816(acc[mi][ni], af[mi], &b2[ni >> 1][(ni & 1) * 2]);
        }
        __syncthreads();
    }

#pragma unroll
    for (int mi = 0; mi < 4; mi++) {
        int row = m0 + wm + mi * 16 + (lane >> 2);
#pragma unroll
        for (int ni = 0; ni < 4; ni++) {
            int col = n0 + wn + ni * 8 + (lane & 3) * 2;
            *(float2*)&C[(size_t)row * N + col]       = make_float2(acc[mi][ni][0], acc[mi][ni][1]);
            *(float2*)&C[(size_t)(row + 8) * N + col] = make_float2(acc[mi][ni][2], acc[mi][ni][3]);
        }
    }
}

// ---------------------------------------------------------------------------
// cos/sin table
// ---------------------------------------------------------------------------
__global__ void cs_table_kernel() {
    int i = blockIdx.x * blockDim.x + threadIdx.x;
    if (i >= S_ * 32) return;
    int pos = i >> 5, p = i & 31;
    double inv = exp(-((double)(2 * p) / 64.0) * log(10000.0));
    double ang = (double)pos * inv;
    g_cs[i] = make_float2((float)cos(ang), (float)sin(ang));
}

// ---------------------------------------------------------------------------
// Fused RoPE (Q,K) + fp16 conversion: Q single, K hi/lo, V hi/lo
// ---------------------------------------------------------------------------
__global__ void rope_split_kernel(const float* __restrict__ q,
                                  const float* __restrict__ k,
                                  const float* __restrict__ v) {
    const int NQ = MROWS * 1024;
    const int NK = MROWS * 256;
    const int NV = MROWS * 256;
    int idx = blockIdx.x * blockDim.x + threadIdx.x;
    if (idx >= NQ + NK + NV) return;

    if (idx < NQ) {                       // Q: rope, single fp16
        int row = idx >> 10; int rem = idx & 1023;
        int head = rem >> 5, p = rem & 31;
        size_t base = (size_t)row * H_ + head * HD;
        int pos = row & (S_ - 1);
        float2 cs = g_cs[pos * 32 + p];
        float x0 = q[base + p], x1 = q[base + p + 32];
        g_qh[base + p]      = __float2half_rn(x0 * cs.x - x1 * cs.y);
        g_qh[base + p + 32] = __float2half_rn(x1 * cs.x + x0 * cs.y);
    } else if (idx < NQ + NK) {           // K: rope, hi/lo
        int i2 = idx - NQ;
        int row = i2 >> 8; int rem = i2 & 255;
        int head = rem >> 5, p = rem & 31;
        size_t base = (size_t)row * KVD + head * HD;
        int pos = row & (S_ - 1);
        float2 cs = g_cs[pos * 32 + p];
        float x0 = k[base + p], x1 = k[base + p + 32];
        float y0 = x0 * cs.x - x1 * cs.y;
        float y1 = x1 * cs.x + x0 * cs.y;
        __half h0 = __float2half_rn(y0), h1 = __float2half_rn(y1);
        g_kh[base + p]      = h0;
        g_kh[base + p + 32] = h1;
        g_kl[base + p]      = __float2half_rn(y0 - __half2float(h0));
        g_kl[base + p + 32] = __float2half_rn(y1 - __half2float(h1));
    } else {                              // V: hi/lo
        int i2 = idx - NQ - NK;
        size_t base = (size_t)(i2 >> 8) * KVD + (i2 & 255) * 2;
        float x0 = v[base], x1 = v[base + 1];
        __half h0 = __float2half_rn(x0), h1 = __float2half_rn(x1);
        g_vh[base]     = h0;
        g_vh[base + 1] = h1;
        g_vl[base]     = __float2half_rn(x0 - __half2float(h0));
        g_vl[base + 1] = __float2half_rn(x1 - __half2float(h1));
    }
}

// ---------------------------------------------------------------------------
// Tensor-core causal flash attention (fp16x2), 2-stage cp.async pipeline.
// Q single fp16; K,V hi/lo. 2 mma passes per fragment group.
// ---------------------------------------------------------------------------
#define ST2 72
#define FA  (64 * ST2 * 2)
#define FSTAGE (4 * FA)
#define FSMEM  (2 * FSTAGE)

__global__ void __launch_bounds__(128)
flash2(const __half* __restrict__ Qh,
       const __half* __restrict__ Kh, const __half* __restrict__ Kl,
       const __half* __restrict__ Vh, const __half* __restrict__ Vl,
       __half* __restrict__ AOh) {
    extern __shared__ char fsm[];
    const uint32_t smem0 = (uint32_t)__cvta_generic_to_shared(fsm);

    const int t = threadIdx.x, lane = t & 31, w = t >> 5;
    const int qb = blockIdx.x, h = blockIdx.y, b = blockIdx.z, kvh = h >> 2;
    const int g = lane >> 3, r = lane & 7;
    const int a_row = (g & 1) * 8 + r, a_k = (g >> 1) * 8;
    const int b_row = (g >> 1) * 8 + r, b_k = (g & 1) * 8;

    const int ntiles = qb + 1;
    const size_t bS = (size_t)(b * S_);

    // stage Q tile through stage-0 Kh buffer
    {
        __half* s0 = (__half*)(fsm);
        const size_t qbase = (bS + qb * 64) * H_ + h * HD;
#pragma unroll
        for (int i = 0; i < 4; i++) {
            int idx = t + i * 128;
            int row = idx >> 3, c = (idx & 7) * 8;
            *(uint4*)&s0[row * ST2 + c] = *(const uint4*)(Qh + qbase + (size_t)row * H_ + c);
        }
    }
    __syncthreads();
    uint32_t qf[4][4];
#pragma unroll
    for (int ks = 0; ks < 4; ks++)
        ldsm4(qf[ks], smem0 + 2u * ((w * 16 + a_row) * ST2 + ks * 16 + a_k));
    __syncthreads();

    auto issue = [&](int kt) {
        if (kt >= ntiles) return;
        uint32_t base = smem0 + (kt & 1) * FSTAGE;
        const size_t kb = (bS + kt * 64) * KVD + kvh * HD;
#pragma unroll
        for (int i = 0; i < 4; i++) {
            int chunk = t + i * 128;
            int row = chunk >> 3, col = (chunk & 7) * 8;
            size_t go = kb + (size_t)row * KVD + col;
            uint32_t so = base + (row * ST2 + col) * 2;
            cp16(so,          Kh + go);
            cp16(so + FA,     Kl + go);
            cp16(so + 2 * FA, Vh + go);
            cp16(so + 3 * FA, Vl + go);
        }
    };

    issue(0); asm volatile("cp.async.commit_group;\n");
    issue(1); asm volatile("cp.async.commit_group;\n");

    float o[8][4];
#pragma unroll
    for (int j = 0; j < 8; j++)
#pragma unroll
        for (int e = 0; e < 4; e++) o[j][e] = 0.f;
    float m0 = -3.0e38f, m1 = -3.0e38f, l0 = 0.f, l1 = 0.f;
    const int qr0 = qb * 64 + w * 16 + (lane >> 2);
    const int qr1 = qr0 + 8;

    for (int kt = 0; kt < ntiles; kt++) {
        asm volatile("cp.async.wait_group 1;\n");
        __syncthreads();

        const uint32_t base = smem0 + (kt & 1) * FSTAGE;
        const uint32_t pKh = base, pKl = base + FA;
        const uint32_t pVh = base + 2 * FA, pVl = base + 3 * FA;
        const int k0 = kt * 64;

        // ---- S = Q K^T (fp16x2) ----
        float s[8][4];
#pragma unroll
        for (int j = 0; j < 8; j++)
#pragma unroll
            for (int e = 0; e < 4; e++) s[j][e] = 0.f;
#pragma unroll
        for (int ks = 0; ks < 4; ks++) {
            uint32_t bh[4][4], bl[4][4];
#pragma unroll
            for (int nb = 0; nb < 4; nb++) {
                ldsm4(bh[nb], pKh + 2u * ((nb * 16 + b_row) * ST2 + ks * 16 + b_k));
                ldsm4(bl[nb], pKl + 2u * ((nb * 16 + b_row) * ST2 + ks * 16 + b_k));
            }
            // pass 1: Q * Kh
#pragma unroll
            for (int nb = 0; nb < 4; nb++)
#pragma unroll
                for (int hn = 0; hn < 2; hn++)
                    mma16816(s[nb * 2 + hn], qf[ks], bh[nb] + hn * 2);
            // pass 2: Q * Kl
#pragma unroll
            for (int nb = 0; nb < 4; nb++)
#pragma unroll
                for (int hn = 0; hn < 2; hn++)
                    mma16816(s[nb * 2 + hn], qf[ks], bl[nb] + hn * 2);
        }

        // ---- scale + causal mask + online softmax ----
        const bool diag = (kt == ntiles - 1);
        float mx0 = -3.0e38f, mx1 = -3.0e38f;
#pragma unroll
        for (int j = 0; j < 8; j++) {
            int colb = k0 + j * 8 + (lane & 3) * 2;
#pragma unroll
            for (int e = 0; e < 4; e++) {
                float val = s[j][e] * 0.125f;
                if (diag) {
                    int col = colb + (e & 1);
                    int qr  = (e < 2) ? qr0 : qr1;
                    if (col > qr) val = -1.0e9f;
                }
                s[j][e] = val;
                if (e < 2) mx0 = fmaxf(mx0, val); else mx1 = fmaxf(mx1, val);
            }
        }
        mx0 = fmaxf(mx0, __shfl_xor_sync(0xffffffffu, mx0, 1));
        mx0 = fmaxf(mx0, __shfl_xor_sync(0xffffffffu, mx0, 2));
        mx1 = fmaxf(mx1, __shfl_xor_sync(0xffffffffu, mx1, 1));
        mx1 = fmaxf(mx1, __shfl_xor_sync(0xffffffffu, mx1, 2));
        float nm0 = fmaxf(m0, mx0), nm1 = fmaxf(m1, mx1);
        float c0 = __expf(m0 - nm0), c1 = __expf(m1 - nm1);
        l0 *= c0; l1 *= c1;
#pragma unroll
        for (int j = 0; j < 8; j++) {
            o[j][0] *= c0; o[j][1] *= c0;
            o[j][2] *= c1; o[j][3] *= c1;
        }
        m0 = nm0; m1 = nm1;
        float rs0 = 0.f, rs1 = 0.f;
#pragma unroll
        for (int j = 0; j < 8; j++) {
#pragma unroll
            for (int e = 0; e < 4; e++) {
                float p = __expf(s[j][e] - ((e < 2) ? m0 : m1));
                s[j][e] = p;
                if (e < 2) rs0 += p; else rs1 += p;
            }
        }
        l0 += rs0; l1 += rs1;

        // ---- P fragments (single fp16) ----
        uint32_t ph[4][4];
#pragma unroll
        for (int kg = 0; kg < 4; kg++)
#pragma unroll
            for (int q2 = 0; q2 < 2; q2++) {
                int j = 2 * kg + q2;
#pragma unroll
                for (int half = 0; half < 2; half++)
                    ph[kg][q2 * 2 + half] = pack_h(s[j][half * 2], s[j][half * 2 + 1]);
            }

        // ---- O += P V (fp16x2) ----
#pragma unroll
        for (int kg = 0; kg < 4; kg++) {
            uint32_t vhf[4][4], vlf[4][4];
#pragma unroll
            for (int dt = 0; dt < 4; dt++) {
                uint32_t vaddr = 2u * ((kg * 16 + (lane & 15)) * ST2 + dt * 16 + (lane >> 4) * 8);
                ldsm4t(vhf[dt], pVh + vaddr);
                ldsm4t(vlf[dt], pVl + vaddr);
            }
            // pass 1: P * Vh
#pragma unroll
            for (int dt = 0; dt < 4; dt++)
#pragma unroll
                for (int hn = 0; hn < 2; hn++)
                    mma16816(o[dt * 2 + hn], ph[kg], vhf[dt] + hn * 2);
            // pass 2: P * Vl
#pragma unroll
            for (int dt = 0; dt < 4; dt++)
#pragma unroll
                for (int hn = 0; hn < 2; hn++)
                    mma16816(o[dt * 2 + hn], ph[kg], vlf[dt] + hn * 2);
        }
        __syncthreads();
        issue(kt + 2);
        asm volatile("cp.async.commit_group;\n");
    }

    l0 += __shfl_xor_sync(0xffffffffu, l0, 1);
    l0 += __shfl_xor_sync(0xffffffffu, l0, 2);
    l1 += __shfl_xor_sync(0xffffffffu, l1, 1);
    l1 += __shfl_xor_sync(0xffffffffu, l1, 2);
    float inv0 = 1.f / l0, inv1 = 1.f / l1;
    const size_t obase = ((size_t)(b * S_) + qb * 64 + w * 16) * H_ + h * HD;
#pragma unroll
    for (int j = 0; j < 8; j++) {
        int col = j * 8 + (lane & 3) * 2;
        size_t off0 = obase + (size_t)(lane >> 2) * H_ + col;
        size_t off1 = obase + (size_t)((lane >> 2) + 8) * H_ + col;
        *(__half2*)&AOh[off0] = __floats2half2_rn(o[j][0] * inv0, o[j][1] * inv0);
        *(__half2*)&AOh[off1] = __floats2half2_rn(o[j][2] * inv1, o[j][3] * inv1);
    }
}

// ---------------------------------------------------------------------------
// inputs: x, position_ids(unused), mask(unused), wq, wk, wv, wo
// ---------------------------------------------------------------------------
extern "C" void kernel_launch(void* const* d_in, const int* in_sizes, int n_in,
                              void* d_out, int out_size) {
    const float* x  = (const float*)d_in[0];
    const float* wq = (const float*)d_in[3];
    const float* wk = (const float*)d_in[4];
    const float* wv = (const float*)d_in[5];
    const float* wo = (const float*)d_in[6];
    float* out = (float*)d_out;

    float *q, *k, *v;
    cudaGetSymbolAddress((void**)&q, g_q);
    cudaGetSymbolAddress((void**)&k, g_k);
    cudaGetSymbolAddress((void**)&v, g_v);
    __half *xh, *wqh, *wql, *wkh, *wkl, *wvh, *wvl, *woh, *wol;
    __half *aoh, *qh, *kh, *kl, *vh, *vl;
    cudaGetSymbolAddress((void**)&xh,  g_xh);
    cudaGetSymbolAddress((void**)&wqh, g_wqh); cudaGetSymbolAddress((void**)&wql, g_wql);
    cudaGetSymbolAddress((void**)&wkh, g_wkh); cudaGetSymbolAddress((void**)&wkl, g_wkl);
    cudaGetSymbolAddress((void**)&wvh, g_wvh); cudaGetSymbolAddress((void**)&wvl, g_wvl);
    cudaGetSymbolAddress((void**)&woh, g_woh); cudaGetSymbolAddress((void**)&wol, g_wol);
    cudaGetSymbolAddress((void**)&aoh, g_aoh);
    cudaGetSymbolAddress((void**)&qh,  g_qh);
    cudaGetSymbolAddress((void**)&kh,  g_kh);  cudaGetSymbolAddress((void**)&kl,  g_kl);
    cudaGetSymbolAddress((void**)&vh,  g_vh);  cudaGetSymbolAddress((void**)&vl,  g_vl);

    cudaFuncSetAttribute(gemm_pre, cudaFuncAttributeMaxDynamicSharedMemorySize, SMEMSZ);
    cudaFuncSetAttribute(flash2,   cudaFuncAttributeMaxDynamicSharedMemorySize, FSMEM);

    // launch order arranged so ncu (-s 5 -c 1) captures the big Q-projection GEMM
    convert_h<<<(MROWS * H_ / 4 + 255) / 256, 256>>>(x, xh, MROWS * H_);       // 0
    split_hl<<<(H_ * H_ / 4 + 255) / 256, 256>>>(wq, wqh, wql, H_ * H_);       // 1
    split_hl<<<(KVD * H_ / 4 + 255) / 256, 256>>>(wk, wkh, wkl, KVD * H_);     // 2
    split_hl<<<(KVD * H_ / 4 + 255) / 256, 256>>>(wv, wvh, wvl, KVD * H_);     // 3
    split_hl<<<(H_ * H_ / 4 + 255) / 256, 256>>>(wo, woh, wol, H_ * H_);       // 4

    dim3 gq(H_ / 128, MROWS / 128);
    dim3 gkv(KVD / 128, MROWS / 128);
    gemm_pre<<<gq, 256, SMEMSZ>>>(xh, wqh, wql, q, MROWS, H_, H_);             // 5 <- profiled
    gemm_pre<<<gkv, 256, SMEMSZ>>>(xh, wkh, wkl, k, MROWS, KVD, H_);
    gemm_pre<<<gkv, 256, SMEMSZ>>>(xh, wvh, wvl, v, MROWS, KVD, H_);

    cs_table_kernel<<<(S_ * 32 + 255) / 256, 256>>>();
    int total = MROWS * 1024 + MROWS * 256 + MROWS * 256;
    rope_split_kernel<<<(total + 255) / 256, 256>>>(q, k, v);

    dim3 ga(S_ / 64, NH, B_);
    flash2<<<ga, 128, FSMEM>>>(qh, kh, kl, vh, vl, aoh);

    gemm_pre<<<gq, 256, SMEMSZ>>>(aoh, woh, wol, out, MROWS, H_, H_);
}